// round 5
// baseline (speedup 1.0000x reference)
#include <cuda_runtime.h>

#define N_NODES 50000
#define N_EDGES 1600000
#define C 256
#define OUTC 10

// Scratch (device globals: allocation-free per harness rules)
__device__ float g_agg[N_NODES * C];    // layer-1 scatter sum -> scaled mean
__device__ float g_h[N_NODES * C];      // layer-1 output (relu)
__device__ float g_agg2[N_NODES * C];   // layer-2 scatter sum -> scaled mean
__device__ int   g_cnt[N_NODES];
__device__ float g_inv[N_NODES];
__device__ int   g_src[N_EDGES];
__device__ int   g_dst[N_EDGES];
__device__ int   g_is64;

// ---------------------------------------------------------------------------
// Detect whether edge_index is int64 or int32.
// If int64 (LE, values < 2^31): every odd int32 word is 0.
// If int32: odd words are node indices; first 4096 all-zero is ~impossible.
__global__ void detect_kernel(const int* __restrict__ ei32) {
    __shared__ int any;
    if (threadIdx.x == 0) any = 0;
    __syncthreads();
    int nz = 0;
    for (int i = threadIdx.x; i < 4096; i += blockDim.x)
        if (ei32[2 * i + 1] != 0) nz = 1;
    if (nz) atomicOr(&any, 1);
    __syncthreads();
    if (threadIdx.x == 0) g_is64 = (any == 0);
}

__global__ void convert_kernel(const void* __restrict__ ei) {
    int e = blockIdx.x * blockDim.x + threadIdx.x;
    if (e >= N_EDGES) return;
    if (g_is64) {
        const long long* __restrict__ p = (const long long*)ei;
        g_src[e] = (int)p[e];
        g_dst[e] = (int)p[N_EDGES + e];
    } else {
        const int* __restrict__ p = (const int*)ei;
        g_src[e] = p[e];
        g_dst[e] = p[N_EDGES + e];
    }
}

// ---------------------------------------------------------------------------
__global__ void init_kernel() {
    int i = blockIdx.x * blockDim.x + threadIdx.x;
    const int n4 = N_NODES * C / 4;   // 3.2M float4
    if (i < n4) {
        float4 z = make_float4(0.f, 0.f, 0.f, 0.f);
        ((float4*)g_agg)[i]  = z;
        ((float4*)g_agg2)[i] = z;
    }
    if (i < N_NODES) g_cnt[i] = 0;
}

__global__ void count_kernel() {
    int e = blockIdx.x * blockDim.x + threadIdx.x;
    if (e < N_EDGES) atomicAdd(&g_cnt[g_dst[e]], 1);
}

__global__ void inv_kernel() {
    int i = blockIdx.x * blockDim.x + threadIdx.x;
    if (i < N_NODES) {
        int c = g_cnt[i];
        g_inv[i] = 1.0f / (float)(c < 1 ? 1 : c);
    }
}

// which==0: feat = x (param), dst = g_agg ; which==1: feat = g_h, dst = g_agg2
__global__ void scatter_kernel(const float* __restrict__ xin, int which) {
    int idx = blockIdx.x * blockDim.x + threadIdx.x;   // N_EDGES*64 = 102.4M
    if (idx >= N_EDGES * 64) return;
    const float* __restrict__ feat = which ? g_h : xin;
    float* __restrict__ agg = which ? g_agg2 : g_agg;
    int e = idx >> 6;
    int c = (idx & 63) << 2;
    int src = __ldg(g_src + e);
    int dst = __ldg(g_dst + e);
    float4 v = *(const float4*)(feat + src * C + c);
    float* d = agg + dst * C + c;
    atomicAdd(d + 0, v.x);
    atomicAdd(d + 1, v.y);
    atomicAdd(d + 2, v.z);
    atomicAdd(d + 3, v.w);
}

__global__ void scale_kernel(int which) {
    int i = blockIdx.x * blockDim.x + threadIdx.x;
    const int n4 = N_NODES * C / 4;
    if (i < n4) {
        float* __restrict__ agg = which ? g_agg2 : g_agg;
        float s = g_inv[i >> 6];   // 64 float4 per row
        float4 v = ((float4*)agg)[i];
        v.x *= s; v.y *= s; v.z *= s; v.w *= s;
        ((float4*)agg)[i] = v;
    }
}

// ---------------------------------------------------------------------------
// Layer-1 GEMM: h = relu( [agg_scaled | x] @ [W1l ; W1r] + b1 )
//   M=50000, N=256, K=512.  BM=128, BN=128, BK=16, 256 threads, 8x8/thread.
#define BM 128
#define BN 128
#define BK 16
#define KTILES 32   // 512 / 16

__global__ __launch_bounds__(256) void gemm1_kernel(
    const float* __restrict__ x,
    const float* __restrict__ W1l, const float* __restrict__ W1r,
    const float* __restrict__ b1) {
    __shared__ __align__(16) float As[2][BK][BM + 4];
    __shared__ __align__(16) float Bs[2][BK][BN];

    const int bm = blockIdx.x * BM;
    const int bn = blockIdx.y * BN;
    const int tid = threadIdx.x;
    const int tx = tid & 15;
    const int ty = tid >> 4;

    float acc[8][8];
#pragma unroll
    for (int i = 0; i < 8; i++)
#pragma unroll
        for (int j = 0; j < 8; j++) acc[i][j] = 0.f;

    // per-thread load positions (each thread loads 2 float4 for A and for B)
    const int pa0 = tid, pa1 = tid + 256;
    const int arow0 = pa0 >> 2, ak0 = (pa0 & 3) << 2;
    const int arow1 = pa1 >> 2, ak1 = (pa1 & 3) << 2;
    const int brow0 = pa0 >> 5, bc0 = (pa0 & 31) << 2;
    const int brow1 = pa1 >> 5, bc1 = (pa1 & 31) << 2;

    float4 ra0, ra1, rb0, rb1;
    const float4 z4 = make_float4(0.f, 0.f, 0.f, 0.f);

    auto fetch = [&](int t) {
        int k0 = t * BK;
        const float* ap;
        const float* bp;
        if (k0 < C) { ap = g_agg + k0;       bp = W1l + k0 * C; }
        else        { ap = x + (k0 - C);     bp = W1r + (k0 - C) * C; }
        ra0 = (bm + arow0 < N_NODES) ? *(const float4*)(ap + (bm + arow0) * C + ak0) : z4;
        ra1 = (bm + arow1 < N_NODES) ? *(const float4*)(ap + (bm + arow1) * C + ak1) : z4;
        rb0 = *(const float4*)(bp + brow0 * C + bn + bc0);
        rb1 = *(const float4*)(bp + brow1 * C + bn + bc1);
    };
    auto put = [&](int buf) {
        As[buf][ak0 + 0][arow0] = ra0.x;
        As[buf][ak0 + 1][arow0] = ra0.y;
        As[buf][ak0 + 2][arow0] = ra0.z;
        As[buf][ak0 + 3][arow0] = ra0.w;
        As[buf][ak1 + 0][arow1] = ra1.x;
        As[buf][ak1 + 1][arow1] = ra1.y;
        As[buf][ak1 + 2][arow1] = ra1.z;
        As[buf][ak1 + 3][arow1] = ra1.w;
        *(float4*)&Bs[buf][brow0][bc0] = rb0;
        *(float4*)&Bs[buf][brow1][bc1] = rb1;
    };

    fetch(0);
    put(0);
    __syncthreads();

    for (int t = 0; t < KTILES; t++) {
        int cur = t & 1;
        if (t + 1 < KTILES) fetch(t + 1);
#pragma unroll
        for (int kk = 0; kk < BK; kk++) {
            float4 a0 = *(const float4*)&As[cur][kk][ty * 8];
            float4 a1 = *(const float4*)&As[cur][kk][ty * 8 + 4];
            float4 b0 = *(const float4*)&Bs[cur][kk][tx * 8];
            float4 b1v = *(const float4*)&Bs[cur][kk][tx * 8 + 4];
            float am[8] = {a0.x, a0.y, a0.z, a0.w, a1.x, a1.y, a1.z, a1.w};
            float bv[8] = {b0.x, b0.y, b0.z, b0.w, b1v.x, b1v.y, b1v.z, b1v.w};
#pragma unroll
            for (int i = 0; i < 8; i++)
#pragma unroll
                for (int j = 0; j < 8; j++) acc[i][j] += am[i] * bv[j];
        }
        if (t + 1 < KTILES) {
            put((t + 1) & 1);
            __syncthreads();
        }
    }

    // epilogue: bias + relu, vectorized stores
    float4 bb0 = *(const float4*)&b1[bn + tx * 8];
    float4 bb1 = *(const float4*)&b1[bn + tx * 8 + 4];
#pragma unroll
    for (int i = 0; i < 8; i++) {
        int row = bm + ty * 8 + i;
        if (row < N_NODES) {
            float4 o0, o1;
            o0.x = fmaxf(acc[i][0] + bb0.x, 0.f);
            o0.y = fmaxf(acc[i][1] + bb0.y, 0.f);
            o0.z = fmaxf(acc[i][2] + bb0.z, 0.f);
            o0.w = fmaxf(acc[i][3] + bb0.w, 0.f);
            o1.x = fmaxf(acc[i][4] + bb1.x, 0.f);
            o1.y = fmaxf(acc[i][5] + bb1.y, 0.f);
            o1.z = fmaxf(acc[i][6] + bb1.z, 0.f);
            o1.w = fmaxf(acc[i][7] + bb1.w, 0.f);
            *(float4*)&g_h[row * C + bn + tx * 8] = o0;
            *(float4*)&g_h[row * C + bn + tx * 8 + 4] = o1;
        }
    }
}

// ---------------------------------------------------------------------------
// Layer-2 GEMM (+ log_softmax): out = log_softmax([agg2_scaled | h] @ [W2l;W2r] + b2)
// warp per node; W transposed into shared for conflict-free float4 reads.
__global__ __launch_bounds__(256) void gemm2_kernel(
    const float* __restrict__ W2l, const float* __restrict__ W2r,
    const float* __restrict__ b2, float* __restrict__ out) {
    __shared__ __align__(16) float Wt[OUTC][2 * C];   // [10][512]
    __shared__ float b2s[OUTC];

    const int tid = threadIdx.x;
    for (int p = tid; p < OUTC * 2 * C; p += 256) {
        int n = p / (2 * C), k = p % (2 * C);
        Wt[n][k] = (k < C) ? W2l[k * OUTC + n] : W2r[(k - C) * OUTC + n];
    }
    if (tid < OUTC) b2s[tid] = b2[tid];
    __syncthreads();

    const int lane = tid & 31;
    const int warp = tid >> 5;
    const int wglobal = blockIdx.x * 8 + warp;
    const int nwarps = gridDim.x * 8;

    for (int node = wglobal; node < N_NODES; node += nwarps) {
        const float4* ar = (const float4*)(g_agg2 + node * C);
        const float4* hr = (const float4*)(g_h + node * C);
        float4 a0 = ar[lane], a1 = ar[lane + 32];
        float4 a2 = hr[lane], a3 = hr[lane + 32];

        float s[OUTC];
#pragma unroll
        for (int n = 0; n < OUTC; n++) {
            const float4* w = (const float4*)&Wt[n][0];
            float4 w0 = w[lane], w1 = w[lane + 32];
            float4 w2 = w[lane + 64], w3 = w[lane + 96];
            float acc = a0.x * w0.x + a0.y * w0.y + a0.z * w0.z + a0.w * w0.w;
            acc += a1.x * w1.x + a1.y * w1.y + a1.z * w1.z + a1.w * w1.w;
            acc += a2.x * w2.x + a2.y * w2.y + a2.z * w2.z + a2.w * w2.w;
            acc += a3.x * w3.x + a3.y * w3.y + a3.z * w3.z + a3.w * w3.w;
            s[n] = acc;
        }
#pragma unroll
        for (int n = 0; n < OUTC; n++) {
#pragma unroll
            for (int off = 16; off; off >>= 1)
                s[n] += __shfl_xor_sync(0xffffffffu, s[n], off);
            s[n] += b2s[n];
        }
        // log_softmax over 10 values (all lanes redundant; lane 0 writes)
        float m = s[0];
#pragma unroll
        for (int n = 1; n < OUTC; n++) m = fmaxf(m, s[n]);
        float se = 0.f;
#pragma unroll
        for (int n = 0; n < OUTC; n++) se += expf(s[n] - m);
        float lse = m + logf(se);
        if (lane == 0) {
#pragma unroll
            for (int n = 0; n < OUTC; n++) out[node * OUTC + n] = s[n] - lse;
        }
    }
}

// ---------------------------------------------------------------------------
extern "C" void kernel_launch(void* const* d_in, const int* in_sizes, int n_in,
                              void* d_out, int out_size) {
    const float* x = (const float*)d_in[0];
    const void* ei = d_in[1];
    const float* W1l = (const float*)d_in[2];
    const float* W1r = (const float*)d_in[3];
    const float* b1 = (const float*)d_in[4];
    const float* W2l = (const float*)d_in[5];
    const float* W2r = (const float*)d_in[6];
    const float* b2 = (const float*)d_in[7];
    float* out = (float*)d_out;

    detect_kernel<<<1, 256>>>((const int*)ei);
    convert_kernel<<<(N_EDGES + 255) / 256, 256>>>(ei);

    const int n4 = N_NODES * C / 4;            // 3.2M
    init_kernel<<<(n4 + 255) / 256, 256>>>();
    count_kernel<<<(N_EDGES + 255) / 256, 256>>>();
    inv_kernel<<<(N_NODES + 255) / 256, 256>>>();

    scatter_kernel<<<(N_EDGES * 64) / 256, 256>>>(x, 0);
    scale_kernel<<<(n4 + 255) / 256, 256>>>(0);

    dim3 g1((N_NODES + BM - 1) / BM, 2);
    gemm1_kernel<<<g1, 256>>>(x, W1l, W1r, b1);

    scatter_kernel<<<(N_EDGES * 64) / 256, 256>>>(x, 1);
    scale_kernel<<<(n4 + 255) / 256, 256>>>(1);

    gemm2_kernel<<<1024, 256>>>(W2l, W2r, b2, out);
}

// round 6
// speedup vs baseline: 3.2228x; 3.2228x over previous
#include <cuda_runtime.h>
#include <float.h>

#define N_NODES 50000
#define N_EDGES 1600000
#define C 256
#define OUTC 10

// Scratch (device globals: allocation-free per harness rules)
__device__ float g_PQ[N_NODES * 2 * C];   // [50K,512]: cols 0..255 = x@W1l (P), 256..511 = x@W1r + b1 (Q)
__device__ float g_h[N_NODES * C];        // layer-1 output (relu)
__device__ float g_Rl[N_NODES * OUTC];    // h @ W2l
__device__ float g_Rr[N_NODES * OUTC];    // h @ W2r + b2
__device__ int   g_cnt[N_NODES];
__device__ float g_inv[N_NODES];
__device__ int   g_rowptr[N_NODES + 1];
__device__ int   g_cur[N_NODES];
__device__ int   g_src[N_EDGES];
__device__ int   g_dst[N_EDGES];
__device__ int   g_nbr[N_EDGES];          // CSR adjacency (src nodes grouped by dst)
__device__ int   g_is64;

// ---------------------------------------------------------------------------
// Detect whether edge_index is int64 or int32 (JAX may silently emit int32).
__global__ void detect_kernel(const int* __restrict__ ei32) {
    __shared__ int any;
    if (threadIdx.x == 0) any = 0;
    __syncthreads();
    int nz = 0;
    for (int i = threadIdx.x; i < 4096; i += blockDim.x)
        if (ei32[2 * i + 1] != 0) nz = 1;
    if (nz) atomicOr(&any, 1);
    __syncthreads();
    if (threadIdx.x == 0) g_is64 = (any == 0);
}

__global__ void convert_kernel(const void* __restrict__ ei) {
    int e = blockIdx.x * blockDim.x + threadIdx.x;
    if (e >= N_EDGES) return;
    if (g_is64) {
        const long long* __restrict__ p = (const long long*)ei;
        g_src[e] = (int)p[e];
        g_dst[e] = (int)p[N_EDGES + e];
    } else {
        const int* __restrict__ p = (const int*)ei;
        g_src[e] = p[e];
        g_dst[e] = p[N_EDGES + e];
    }
}

__global__ void zero_cnt_kernel() {
    int i = blockIdx.x * blockDim.x + threadIdx.x;
    if (i < N_NODES) g_cnt[i] = 0;
}

__global__ void count_kernel() {
    int e = blockIdx.x * blockDim.x + threadIdx.x;
    if (e < N_EDGES) atomicAdd(&g_cnt[g_dst[e]], 1);
}

__global__ void inv_kernel() {
    int i = blockIdx.x * blockDim.x + threadIdx.x;
    if (i < N_NODES) {
        int c = g_cnt[i];
        g_inv[i] = 1.0f / (float)(c < 1 ? 1 : c);
    }
}

// Single-block exclusive scan of g_cnt -> g_rowptr (and g_cur copy).
__global__ __launch_bounds__(1024) void scan_kernel() {
    __shared__ int partial[1024];
    const int T = 1024;
    const int CH = (N_NODES + T - 1) / T;   // 49
    int tid = threadIdx.x;
    int base = tid * CH;
    int s = 0;
    for (int i = 0; i < CH; i++) {
        int idx = base + i;
        if (idx < N_NODES) s += g_cnt[idx];
    }
    partial[tid] = s;
    __syncthreads();
    for (int off = 1; off < T; off <<= 1) {
        int v = (tid >= off) ? partial[tid - off] : 0;
        __syncthreads();
        partial[tid] += v;
        __syncthreads();
    }
    int run = (tid == 0) ? 0 : partial[tid - 1];
    for (int i = 0; i < CH; i++) {
        int idx = base + i;
        if (idx < N_NODES) {
            g_rowptr[idx] = run;
            g_cur[idx] = run;
            run += g_cnt[idx];
        }
    }
    if (tid == T - 1) g_rowptr[N_NODES] = run;
}

__global__ void fill_kernel() {
    int e = blockIdx.x * blockDim.x + threadIdx.x;
    if (e < N_EDGES) {
        int dst = g_dst[e];
        int slot = atomicAdd(&g_cur[dst], 1);
        g_nbr[slot] = g_src[e];
    }
}

// ---------------------------------------------------------------------------
// GEMM1: PQ = x @ [W1l | W1r]  (+ b1 on the right half)
//   M=50000, N=512, K=256.  BM=128, BN=128, BK=16, 256 threads, 8x8/thread.
#define BM 128
#define BN 128
#define BK 16
#define KTILES (C / BK)   // 16

__global__ __launch_bounds__(256) void gemm1_kernel(
    const float* __restrict__ x,
    const float* __restrict__ W1l, const float* __restrict__ W1r,
    const float* __restrict__ b1) {
    __shared__ __align__(16) float As[2][BK][BM + 4];
    __shared__ __align__(16) float Bs[2][BK][BN];

    const int bm = blockIdx.x * BM;
    const int bn = blockIdx.y * BN;          // 0,128,256,384
    const int tid = threadIdx.x;
    const int tx = tid & 15;
    const int ty = tid >> 4;

    const float* __restrict__ Wb = (bn < C) ? W1l : W1r;
    const int bn_loc = bn & (C - 1);

    float acc[8][8];
#pragma unroll
    for (int i = 0; i < 8; i++)
#pragma unroll
        for (int j = 0; j < 8; j++) acc[i][j] = 0.f;

    const int pa0 = tid, pa1 = tid + 256;
    const int arow0 = pa0 >> 2, ak0 = (pa0 & 3) << 2;
    const int arow1 = pa1 >> 2, ak1 = (pa1 & 3) << 2;
    const int brow0 = pa0 >> 5, bc0 = (pa0 & 31) << 2;
    const int brow1 = pa1 >> 5, bc1 = (pa1 & 31) << 2;

    float4 ra0, ra1, rb0, rb1;
    const float4 z4 = make_float4(0.f, 0.f, 0.f, 0.f);

    auto fetch = [&](int t) {
        int k0 = t * BK;
        ra0 = (bm + arow0 < N_NODES) ? *(const float4*)(x + (bm + arow0) * C + k0 + ak0) : z4;
        ra1 = (bm + arow1 < N_NODES) ? *(const float4*)(x + (bm + arow1) * C + k0 + ak1) : z4;
        rb0 = *(const float4*)(Wb + (k0 + brow0) * C + bn_loc + bc0);
        rb1 = *(const float4*)(Wb + (k0 + brow1) * C + bn_loc + bc1);
    };
    auto put = [&](int buf) {
        As[buf][ak0 + 0][arow0] = ra0.x;
        As[buf][ak0 + 1][arow0] = ra0.y;
        As[buf][ak0 + 2][arow0] = ra0.z;
        As[buf][ak0 + 3][arow0] = ra0.w;
        As[buf][ak1 + 0][arow1] = ra1.x;
        As[buf][ak1 + 1][arow1] = ra1.y;
        As[buf][ak1 + 2][arow1] = ra1.z;
        As[buf][ak1 + 3][arow1] = ra1.w;
        *(float4*)&Bs[buf][brow0][bc0] = rb0;
        *(float4*)&Bs[buf][brow1][bc1] = rb1;
    };

    fetch(0);
    put(0);
    __syncthreads();

    for (int t = 0; t < KTILES; t++) {
        int cur = t & 1;
        if (t + 1 < KTILES) fetch(t + 1);
#pragma unroll
        for (int kk = 0; kk < BK; kk++) {
            float4 a0 = *(const float4*)&As[cur][kk][ty * 8];
            float4 a1 = *(const float4*)&As[cur][kk][ty * 8 + 4];
            float4 b0 = *(const float4*)&Bs[cur][kk][tx * 8];
            float4 b1v = *(const float4*)&Bs[cur][kk][tx * 8 + 4];
            float am[8] = {a0.x, a0.y, a0.z, a0.w, a1.x, a1.y, a1.z, a1.w};
            float bv[8] = {b0.x, b0.y, b0.z, b0.w, b1v.x, b1v.y, b1v.z, b1v.w};
#pragma unroll
            for (int i = 0; i < 8; i++)
#pragma unroll
                for (int j = 0; j < 8; j++) acc[i][j] += am[i] * bv[j];
        }
        if (t + 1 < KTILES) {
            put((t + 1) & 1);
            __syncthreads();
        }
    }

    // epilogue: +b1 on right half (Q), no relu (relu comes after aggregation)
    float4 bb0 = z4, bb1 = z4;
    if (bn >= C) {
        bb0 = *(const float4*)&b1[bn_loc + tx * 8];
        bb1 = *(const float4*)&b1[bn_loc + tx * 8 + 4];
    }
#pragma unroll
    for (int i = 0; i < 8; i++) {
        int row = bm + ty * 8 + i;
        if (row < N_NODES) {
            float4 o0, o1;
            o0.x = acc[i][0] + bb0.x;
            o0.y = acc[i][1] + bb0.y;
            o0.z = acc[i][2] + bb0.z;
            o0.w = acc[i][3] + bb0.w;
            o1.x = acc[i][4] + bb1.x;
            o1.y = acc[i][5] + bb1.y;
            o1.z = acc[i][6] + bb1.z;
            o1.w = acc[i][7] + bb1.w;
            *(float4*)&g_PQ[row * (2 * C) + bn + tx * 8] = o0;
            *(float4*)&g_PQ[row * (2 * C) + bn + tx * 8 + 4] = o1;
        }
    }
}

// ---------------------------------------------------------------------------
// Gather1: h[n] = relu( mean_{j in N(n)} P[j] + Q[n] )   (CSR, no atomics)
// One block per node, thread = channel.
__global__ __launch_bounds__(256) void gather1_kernel() {
    __shared__ int nb[256];
    const int n = blockIdx.x;
    const int c = threadIdx.x;
    const int beg = g_rowptr[n];
    const int end = g_rowptr[n + 1];

    float s0 = 0.f, s1 = 0.f, s2 = 0.f, s3 = 0.f;
    for (int j0 = beg; j0 < end; j0 += 256) {
        int cnt = min(256, end - j0);
        __syncthreads();
        if (c < cnt) nb[c] = g_nbr[j0 + c];
        __syncthreads();
        int j = 0;
        for (; j + 4 <= cnt; j += 4) {
            s0 += g_PQ[nb[j + 0] * (2 * C) + c];
            s1 += g_PQ[nb[j + 1] * (2 * C) + c];
            s2 += g_PQ[nb[j + 2] * (2 * C) + c];
            s3 += g_PQ[nb[j + 3] * (2 * C) + c];
        }
        for (; j < cnt; j++) s0 += g_PQ[nb[j] * (2 * C) + c];
    }
    float sum = (s0 + s1) + (s2 + s3);
    float q = g_PQ[n * (2 * C) + C + c];
    float h = fmaf(sum, g_inv[n], q);
    g_h[n * C + c] = fmaxf(h, 0.f);
}

// ---------------------------------------------------------------------------
// GEMM2: Rl = h @ W2l ; Rr = h @ W2r + b2.  Warp per node, K=256, N=10 each.
__global__ __launch_bounds__(256) void gemm2_kernel(
    const float* __restrict__ W2l, const float* __restrict__ W2r,
    const float* __restrict__ b2) {
    __shared__ __align__(16) float Wt[2 * OUTC][C];   // [20][256] transposed
    __shared__ float b2s[OUTC];

    const int tid = threadIdx.x;
    for (int p = tid; p < 2 * OUTC * C; p += 256) {
        int n = p / C, k = p % C;
        Wt[n][k] = (n < OUTC) ? W2l[k * OUTC + n] : W2r[k * OUTC + (n - OUTC)];
    }
    if (tid < OUTC) b2s[tid] = b2[tid];
    __syncthreads();

    const int lane = tid & 31;
    const int warp = tid >> 5;
    const int node = blockIdx.x * 8 + warp;
    if (node >= N_NODES) return;

    const float4* hr = (const float4*)(g_h + node * C);
    float4 h0 = hr[lane], h1 = hr[lane + 32];

    float s[2 * OUTC];
#pragma unroll
    for (int n = 0; n < 2 * OUTC; n++) {
        const float4* w = (const float4*)&Wt[n][0];
        float4 w0 = w[lane], w1 = w[lane + 32];
        float acc = h0.x * w0.x + h0.y * w0.y + h0.z * w0.z + h0.w * w0.w;
        acc += h1.x * w1.x + h1.y * w1.y + h1.z * w1.z + h1.w * w1.w;
#pragma unroll
        for (int off = 16; off; off >>= 1)
            acc += __shfl_xor_sync(0xffffffffu, acc, off);
        s[n] = acc;
    }
    if (lane == 0) {
#pragma unroll
        for (int n = 0; n < OUTC; n++) {
            g_Rl[node * OUTC + n] = s[n];
            g_Rr[node * OUTC + n] = s[OUTC + n] + b2s[n];
        }
    }
}

// ---------------------------------------------------------------------------
// Final: out[n] = log_softmax( mean_{j in N(n)} Rl[j] + Rr[n] )
// Warp per node; lanes 0..9 own the 10 channels.
__global__ __launch_bounds__(256) void final_kernel(float* __restrict__ out) {
    const int tid = threadIdx.x;
    const int lane = tid & 31;
    const int warp = tid >> 5;
    const int node = blockIdx.x * 8 + warp;
    if (node >= N_NODES) return;

    const int beg = g_rowptr[node];
    const int end = g_rowptr[node + 1];

    float sum = 0.f;
    const int t = lane;   // channel if <10
    for (int j = beg; j < end; j++) {
        int src = g_nbr[j];   // same address across lanes -> broadcast
        if (t < OUTC) sum += g_Rl[src * OUTC + t];
    }
    float s = -FLT_MAX;
    if (t < OUTC) s = fmaf(sum, g_inv[node], g_Rr[node * OUTC + t]);

    // warp max over lanes (inactive lanes carry -FLT_MAX)
    float m = s;
#pragma unroll
    for (int off = 16; off; off >>= 1)
        m = fmaxf(m, __shfl_xor_sync(0xffffffffu, m, off));
    float e = (t < OUTC) ? expf(s - m) : 0.f;
#pragma unroll
    for (int off = 16; off; off >>= 1)
        e += __shfl_xor_sync(0xffffffffu, e, off);
    float lse = m + logf(e);
    if (t < OUTC) out[node * OUTC + t] = s - lse;
}

// ---------------------------------------------------------------------------
extern "C" void kernel_launch(void* const* d_in, const int* in_sizes, int n_in,
                              void* d_out, int out_size) {
    const float* x = (const float*)d_in[0];
    const void* ei = d_in[1];
    const float* W1l = (const float*)d_in[2];
    const float* W1r = (const float*)d_in[3];
    const float* b1 = (const float*)d_in[4];
    const float* W2l = (const float*)d_in[5];
    const float* W2r = (const float*)d_in[6];
    const float* b2 = (const float*)d_in[7];
    float* out = (float*)d_out;

    detect_kernel<<<1, 256>>>((const int*)ei);
    convert_kernel<<<(N_EDGES + 255) / 256, 256>>>(ei);

    zero_cnt_kernel<<<(N_NODES + 255) / 256, 256>>>();
    count_kernel<<<(N_EDGES + 255) / 256, 256>>>();
    inv_kernel<<<(N_NODES + 255) / 256, 256>>>();
    scan_kernel<<<1, 1024>>>();
    fill_kernel<<<(N_EDGES + 255) / 256, 256>>>();

    dim3 g1((N_NODES + BM - 1) / BM, 4);   // 391 x 4
    gemm1_kernel<<<g1, 256>>>(x, W1l, W1r, b1);

    gather1_kernel<<<N_NODES, 256>>>();

    gemm2_kernel<<<(N_NODES + 7) / 8, 256>>>(W2l, W2r, b2);
    final_kernel<<<(N_NODES + 7) / 8, 256>>>(out);
}

// round 13
// speedup vs baseline: 3.9585x; 1.2283x over previous
#include <cuda_runtime.h>
#include <mma.h>
#include <cstdint>
#include <float.h>

using namespace nvcuda;

#define N_NODES 50000
#define M_PAD 50048           // N_NODES rounded up to 128
#define N_EDGES 1600000
#define C 256
#define OUTC 10

// Scratch (device globals: allocation-free per harness rules)
__device__ float g_PQ[M_PAD * 2 * C];     // [50048,512]: 0..255 = x@W1l (P), 256..511 = x@W1r (Q, bias added later)
__device__ float g_h[N_NODES * C];        // layer-1 output (relu)
__device__ float g_Rl[N_NODES * OUTC];    // h @ W2l
__device__ float g_Rr[N_NODES * OUTC];    // h @ W2r + b2
__device__ int   g_cnt[N_NODES];
__device__ float g_inv[N_NODES];
__device__ int   g_rowptr[N_NODES + 1];
__device__ int   g_cur[N_NODES];
__device__ int   g_src[N_EDGES];
__device__ int   g_dst[N_EDGES];
__device__ int   g_nbr[N_EDGES];          // CSR adjacency (src nodes grouped by dst)
__device__ int   g_is64;

// ---------------------------------------------------------------------------
// Edge preprocessing
__global__ void detect_kernel(const int* __restrict__ ei32) {
    __shared__ int any;
    if (threadIdx.x == 0) any = 0;
    __syncthreads();
    int nz = 0;
    for (int i = threadIdx.x; i < 4096; i += blockDim.x)
        if (ei32[2 * i + 1] != 0) nz = 1;
    if (nz) atomicOr(&any, 1);
    __syncthreads();
    if (threadIdx.x == 0) g_is64 = (any == 0);
}

__global__ void convert_kernel(const void* __restrict__ ei) {
    int e = blockIdx.x * blockDim.x + threadIdx.x;
    if (e >= N_EDGES) return;
    if (g_is64) {
        const long long* __restrict__ p = (const long long*)ei;
        g_src[e] = (int)p[e];
        g_dst[e] = (int)p[N_EDGES + e];
    } else {
        const int* __restrict__ p = (const int*)ei;
        g_src[e] = p[e];
        g_dst[e] = p[N_EDGES + e];
    }
}

__global__ void zero_cnt_kernel() {
    int i = blockIdx.x * blockDim.x + threadIdx.x;
    if (i < N_NODES) g_cnt[i] = 0;
}

__global__ void count_kernel() {
    int e = blockIdx.x * blockDim.x + threadIdx.x;
    if (e < N_EDGES) atomicAdd(&g_cnt[g_dst[e]], 1);
}

__global__ void inv_kernel() {
    int i = blockIdx.x * blockDim.x + threadIdx.x;
    if (i < N_NODES) {
        int c = g_cnt[i];
        g_inv[i] = 1.0f / (float)(c < 1 ? 1 : c);
    }
}

__global__ __launch_bounds__(1024) void scan_kernel() {
    __shared__ int partial[1024];
    const int T = 1024;
    const int CH = (N_NODES + T - 1) / T;
    int tid = threadIdx.x;
    int base = tid * CH;
    int s = 0;
    for (int i = 0; i < CH; i++) {
        int idx = base + i;
        if (idx < N_NODES) s += g_cnt[idx];
    }
    partial[tid] = s;
    __syncthreads();
    for (int off = 1; off < T; off <<= 1) {
        int v = (tid >= off) ? partial[tid - off] : 0;
        __syncthreads();
        partial[tid] += v;
        __syncthreads();
    }
    int run = (tid == 0) ? 0 : partial[tid - 1];
    for (int i = 0; i < CH; i++) {
        int idx = base + i;
        if (idx < N_NODES) {
            g_rowptr[idx] = run;
            g_cur[idx] = run;
            run += g_cnt[idx];
        }
    }
    if (tid == T - 1) g_rowptr[N_NODES] = run;
}

__global__ void fill_kernel() {
    int e = blockIdx.x * blockDim.x + threadIdx.x;
    if (e < N_EDGES) {
        int dst = g_dst[e];
        int slot = atomicAdd(&g_cur[dst], 1);
        g_nbr[slot] = g_src[e];
    }
}

// ---------------------------------------------------------------------------
// GEMM1 via WMMA tf32: PQ = x @ [W1l | W1r]   (bias b1 applied in gather1)
//   M=50048(pad), N=512, K=256.  BM=128, BN=128, BK=16, 256 threads.
//   8 warps as 4(m) x 2(n); warp tile 32x64 = 2x4 m16n16k8 wmma tiles.
#define BM 128
#define BN 128
#define BK 16
#define KTILES (C / BK)   // 16

__global__ __launch_bounds__(256) void gemm1_kernel(
    const float* __restrict__ x,
    const float* __restrict__ W1l, const float* __restrict__ W1r) {
    __shared__ __align__(16) float As[2][BK][BM + 4];   // A[k][m]  (col_major A)
    __shared__ __align__(16) float Bs[2][BK][BN + 4];   // B[k][n]  (row_major B)

    const int bm = blockIdx.x * BM;
    const int bn = blockIdx.y * BN;          // 0,128,256,384
    const int tid = threadIdx.x;
    const int wid = tid >> 5;
    const int wm = (wid & 3) * 32;           // warp m-offset in tile
    const int wn = (wid >> 2) * 64;          // warp n-offset in tile

    const float* __restrict__ Wb = (bn < C) ? W1l : W1r;
    const int bn_loc = bn & (C - 1);

    wmma::fragment<wmma::accumulator, 16, 16, 8, float> acc[2][4];
#pragma unroll
    for (int mi = 0; mi < 2; mi++)
#pragma unroll
        for (int ni = 0; ni < 4; ni++) wmma::fill_fragment(acc[mi][ni], 0.f);

    // loader positions (each thread: 2 float4 for A, 2 for B) — proven R6 pattern
    const int pa0 = tid, pa1 = tid + 256;
    const int arow0 = pa0 >> 2, ak0 = (pa0 & 3) << 2;
    const int arow1 = pa1 >> 2, ak1 = (pa1 & 3) << 2;
    const int brow0 = pa0 >> 5, bc0 = (pa0 & 31) << 2;
    const int brow1 = pa1 >> 5, bc1 = (pa1 & 31) << 2;

    float4 ra0, ra1, rb0, rb1;
    const float4 z4 = make_float4(0.f, 0.f, 0.f, 0.f);

    auto fetch = [&](int t) {
        int k0 = t * BK;
        ra0 = (bm + arow0 < N_NODES) ? *(const float4*)(x + (bm + arow0) * C + k0 + ak0) : z4;
        ra1 = (bm + arow1 < N_NODES) ? *(const float4*)(x + (bm + arow1) * C + k0 + ak1) : z4;
        rb0 = *(const float4*)(Wb + (k0 + brow0) * C + bn_loc + bc0);
        rb1 = *(const float4*)(Wb + (k0 + brow1) * C + bn_loc + bc1);
    };
    auto put = [&](int buf) {
        // tf32-round once at SMEM store; wmma loads raw after that
        As[buf][ak0 + 0][arow0] = wmma::__float_to_tf32(ra0.x);
        As[buf][ak0 + 1][arow0] = wmma::__float_to_tf32(ra0.y);
        As[buf][ak0 + 2][arow0] = wmma::__float_to_tf32(ra0.z);
        As[buf][ak0 + 3][arow0] = wmma::__float_to_tf32(ra0.w);
        As[buf][ak1 + 0][arow1] = wmma::__float_to_tf32(ra1.x);
        As[buf][ak1 + 1][arow1] = wmma::__float_to_tf32(ra1.y);
        As[buf][ak1 + 2][arow1] = wmma::__float_to_tf32(ra1.z);
        As[buf][ak1 + 3][arow1] = wmma::__float_to_tf32(ra1.w);
        float4 tb0 = make_float4(wmma::__float_to_tf32(rb0.x), wmma::__float_to_tf32(rb0.y),
                                 wmma::__float_to_tf32(rb0.z), wmma::__float_to_tf32(rb0.w));
        float4 tb1 = make_float4(wmma::__float_to_tf32(rb1.x), wmma::__float_to_tf32(rb1.y),
                                 wmma::__float_to_tf32(rb1.z), wmma::__float_to_tf32(rb1.w));
        *(float4*)&Bs[buf][brow0][bc0] = tb0;
        *(float4*)&Bs[buf][brow1][bc1] = tb1;
    };

    fetch(0);
    put(0);
    __syncthreads();

    for (int t = 0; t < KTILES; t++) {
        int cur = t & 1;
        if (t + 1 < KTILES) fetch(t + 1);

#pragma unroll
        for (int kk = 0; kk < BK; kk += 8) {
            wmma::fragment<wmma::matrix_a, 16, 16, 8, wmma::precision::tf32, wmma::col_major> af[2];
            wmma::fragment<wmma::matrix_b, 16, 16, 8, wmma::precision::tf32, wmma::row_major> bf[4];
#pragma unroll
            for (int mi = 0; mi < 2; mi++)
                wmma::load_matrix_sync(af[mi], &As[cur][kk][wm + mi * 16], BM + 4);
#pragma unroll
            for (int ni = 0; ni < 4; ni++)
                wmma::load_matrix_sync(bf[ni], &Bs[cur][kk][wn + ni * 16], BN + 4);
#pragma unroll
            for (int mi = 0; mi < 2; mi++)
#pragma unroll
                for (int ni = 0; ni < 4; ni++)
                    wmma::mma_sync(acc[mi][ni], af[mi], bf[ni], acc[mi][ni]);
        }

        if (t + 1 < KTILES) {
            put((t + 1) & 1);
            __syncthreads();
        }
    }

    // Epilogue: direct fragment stores — g_PQ is padded to M_PAD rows, no bounds.
#pragma unroll
    for (int mi = 0; mi < 2; mi++) {
        int row0 = bm + wm + mi * 16;
#pragma unroll
        for (int ni = 0; ni < 4; ni++) {
            int col0 = bn + wn + ni * 16;
            wmma::store_matrix_sync(&g_PQ[row0 * (2 * C) + col0], acc[mi][ni],
                                    2 * C, wmma::mem_row_major);
        }
    }
}

// ---------------------------------------------------------------------------
// Gather1: h[n] = relu( mean_{j in N(n)} P[j] + Q[n] + b1 )   (CSR, no atomics)
__global__ __launch_bounds__(256) void gather1_kernel(const float* __restrict__ b1) {
    __shared__ int nb[256];
    const int n = blockIdx.x;
    const int c = threadIdx.x;
    const int beg = g_rowptr[n];
    const int end = g_rowptr[n + 1];

    float s0 = 0.f, s1 = 0.f, s2 = 0.f, s3 = 0.f;
    for (int j0 = beg; j0 < end; j0 += 256) {
        int cnt = min(256, end - j0);
        __syncthreads();
        if (c < cnt) nb[c] = g_nbr[j0 + c];
        __syncthreads();
        int j = 0;
        for (; j + 4 <= cnt; j += 4) {
            s0 += g_PQ[nb[j + 0] * (2 * C) + c];
            s1 += g_PQ[nb[j + 1] * (2 * C) + c];
            s2 += g_PQ[nb[j + 2] * (2 * C) + c];
            s3 += g_PQ[nb[j + 3] * (2 * C) + c];
        }
        for (; j < cnt; j++) s0 += g_PQ[nb[j] * (2 * C) + c];
    }
    float sum = (s0 + s1) + (s2 + s3);
    float q = g_PQ[n * (2 * C) + C + c] + b1[c];
    float h = fmaf(sum, g_inv[n], q);
    g_h[n * C + c] = fmaxf(h, 0.f);
}

// ---------------------------------------------------------------------------
// GEMM2: Rl = h @ W2l ; Rr = h @ W2r + b2.  Warp per node, K=256, N=10 each.
__global__ __launch_bounds__(256) void gemm2_kernel(
    const float* __restrict__ W2l, const float* __restrict__ W2r,
    const float* __restrict__ b2) {
    __shared__ __align__(16) float Wt[2 * OUTC][C];
    __shared__ float b2s[OUTC];

    const int tid = threadIdx.x;
    for (int p = tid; p < 2 * OUTC * C; p += 256) {
        int n = p / C, k = p % C;
        Wt[n][k] = (n < OUTC) ? W2l[k * OUTC + n] : W2r[k * OUTC + (n - OUTC)];
    }
    if (tid < OUTC) b2s[tid] = b2[tid];
    __syncthreads();

    const int lane = tid & 31;
    const int warp = tid >> 5;
    const int node = blockIdx.x * 8 + warp;
    if (node >= N_NODES) return;

    const float4* hr = (const float4*)(g_h + node * C);
    float4 h0 = hr[lane], h1 = hr[lane + 32];

    float s[2 * OUTC];
#pragma unroll
    for (int n = 0; n < 2 * OUTC; n++) {
        const float4* w = (const float4*)&Wt[n][0];
        float4 w0 = w[lane], w1 = w[lane + 32];
        float acc = h0.x * w0.x + h0.y * w0.y + h0.z * w0.z + h0.w * w0.w;
        acc += h1.x * w1.x + h1.y * w1.y + h1.z * w1.z + h1.w * w1.w;
#pragma unroll
        for (int off = 16; off; off >>= 1)
            acc += __shfl_xor_sync(0xffffffffu, acc, off);
        s[n] = acc;
    }
    if (lane == 0) {
#pragma unroll
        for (int n = 0; n < OUTC; n++) {
            g_Rl[node * OUTC + n] = s[n];
            g_Rr[node * OUTC + n] = s[OUTC + n] + b2s[n];
        }
    }
}

// ---------------------------------------------------------------------------
// Final: out[n] = log_softmax( mean_{j in N(n)} Rl[j] + Rr[n] )
__global__ __launch_bounds__(256) void final_kernel(float* __restrict__ out) {
    const int tid = threadIdx.x;
    const int lane = tid & 31;
    const int warp = tid >> 5;
    const int node = blockIdx.x * 8 + warp;
    if (node >= N_NODES) return;

    const int beg = g_rowptr[node];
    const int end = g_rowptr[node + 1];

    float sum = 0.f;
    const int t = lane;
    for (int j = beg; j < end; j++) {
        int src = g_nbr[j];
        if (t < OUTC) sum += g_Rl[src * OUTC + t];
    }
    float s = -FLT_MAX;
    if (t < OUTC) s = fmaf(sum, g_inv[node], g_Rr[node * OUTC + t]);

    float m = s;
#pragma unroll
    for (int off = 16; off; off >>= 1)
        m = fmaxf(m, __shfl_xor_sync(0xffffffffu, m, off));
    float e = (t < OUTC) ? expf(s - m) : 0.f;
#pragma unroll
    for (int off = 16; off; off >>= 1)
        e += __shfl_xor_sync(0xffffffffu, e, off);
    float lse = m + logf(e);
    if (t < OUTC) out[node * OUTC + t] = s - lse;
}

// ---------------------------------------------------------------------------
extern "C" void kernel_launch(void* const* d_in, const int* in_sizes, int n_in,
                              void* d_out, int out_size) {
    const float* x = (const float*)d_in[0];
    const void* ei = d_in[1];
    const float* W1l = (const float*)d_in[2];
    const float* W1r = (const float*)d_in[3];
    const float* b1 = (const float*)d_in[4];
    const float* W2l = (const float*)d_in[5];
    const float* W2r = (const float*)d_in[6];
    const float* b2 = (const float*)d_in[7];
    float* out = (float*)d_out;

    detect_kernel<<<1, 256>>>((const int*)ei);
    convert_kernel<<<(N_EDGES + 255) / 256, 256>>>(ei);

    zero_cnt_kernel<<<(N_NODES + 255) / 256, 256>>>();
    count_kernel<<<(N_EDGES + 255) / 256, 256>>>();
    inv_kernel<<<(N_NODES + 255) / 256, 256>>>();
    scan_kernel<<<1, 1024>>>();
    fill_kernel<<<(N_EDGES + 255) / 256, 256>>>();

    dim3 g1(M_PAD / BM, 4);   // 391 x 4 (N=512)
    gemm1_kernel<<<g1, 256>>>(x, W1l, W1r);

    gather1_kernel<<<N_NODES, 256>>>(b1);

    gemm2_kernel<<<(N_NODES + 7) / 8, 256>>>(W2l, W2r, b2);
    final_kernel<<<(N_NODES + 7) / 8, 256>>>(out);
}

// round 15
// speedup vs baseline: 3.9810x; 1.0057x over previous
#include <cuda_runtime.h>
#include <mma.h>
#include <cstdint>
#include <float.h>

using namespace nvcuda;

#define N_NODES 50000
#define M_PAD 50048           // N_NODES rounded up to 128
#define N_EDGES 1600000
#define C 256
#define OUTC 10

// Scratch (device globals: allocation-free per harness rules)
__device__ float g_PQ[M_PAD * 2 * C];     // [50048,512]: 0..255 = x@W1l (P), 256..511 = x@W1r (Q, bias in gather)
__device__ float g_h[N_NODES * C];        // layer-1 output (relu)
__device__ float g_Rl[N_NODES * OUTC];    // h @ W2l
__device__ float g_Rr[N_NODES * OUTC];    // h @ W2r + b2
__device__ int   g_cnt[N_NODES];
__device__ float g_inv[N_NODES];
__device__ int   g_rowptr[N_NODES + 1];
__device__ int   g_cur[N_NODES];
__device__ int   g_src[N_EDGES];
__device__ int   g_dst[N_EDGES];
__device__ int   g_nbr[N_EDGES];          // CSR adjacency (src nodes grouped by dst)
__device__ int   g_is64;

// ---------------------------------------------------------------------------
__device__ __forceinline__ uint32_t smem_u32(const void* p) {
    uint32_t a;
    asm("{ .reg .u64 t; cvta.to.shared.u64 t, %1; cvt.u32.u64 %0, t; }" : "=r"(a) : "l"(p));
    return a;
}
__device__ __forceinline__ void cp16(uint32_t dst, const void* src, bool pred) {
    int sz = pred ? 16 : 0;
    asm volatile("cp.async.cg.shared.global [%0], [%1], 16, %2;"
                 :: "r"(dst), "l"(src), "r"(sz));
}

// ---------------------------------------------------------------------------
// Edge preprocessing
__global__ void detect_kernel(const int* __restrict__ ei32) {
    __shared__ int any;
    if (threadIdx.x == 0) any = 0;
    __syncthreads();
    int nz = 0;
    for (int i = threadIdx.x; i < 4096; i += blockDim.x)
        if (ei32[2 * i + 1] != 0) nz = 1;
    if (nz) atomicOr(&any, 1);
    __syncthreads();
    if (threadIdx.x == 0) g_is64 = (any == 0);
}

__global__ void zero_cnt_kernel() {
    int i = blockIdx.x * blockDim.x + threadIdx.x;
    if (i < N_NODES) g_cnt[i] = 0;
}

// convert + degree count fused (one pass over edges)
__global__ void convert_count_kernel(const void* __restrict__ ei) {
    int e = blockIdx.x * blockDim.x + threadIdx.x;
    if (e >= N_EDGES) return;
    int s, d;
    if (g_is64) {
        const long long* __restrict__ p = (const long long*)ei;
        s = (int)p[e];
        d = (int)p[N_EDGES + e];
    } else {
        const int* __restrict__ p = (const int*)ei;
        s = p[e];
        d = p[N_EDGES + e];
    }
    g_src[e] = s;
    g_dst[e] = d;
    atomicAdd(&g_cnt[d], 1);
}

__global__ void inv_kernel() {
    int i = blockIdx.x * blockDim.x + threadIdx.x;
    if (i < N_NODES) {
        int c = g_cnt[i];
        g_inv[i] = 1.0f / (float)(c < 1 ? 1 : c);
    }
}

__global__ __launch_bounds__(1024) void scan_kernel() {
    __shared__ int partial[1024];
    const int T = 1024;
    const int CH = (N_NODES + T - 1) / T;
    int tid = threadIdx.x;
    int base = tid * CH;
    int s = 0;
    for (int i = 0; i < CH; i++) {
        int idx = base + i;
        if (idx < N_NODES) s += g_cnt[idx];
    }
    partial[tid] = s;
    __syncthreads();
    for (int off = 1; off < T; off <<= 1) {
        int v = (tid >= off) ? partial[tid - off] : 0;
        __syncthreads();
        partial[tid] += v;
        __syncthreads();
    }
    int run = (tid == 0) ? 0 : partial[tid - 1];
    for (int i = 0; i < CH; i++) {
        int idx = base + i;
        if (idx < N_NODES) {
            g_rowptr[idx] = run;
            g_cur[idx] = run;
            run += g_cnt[idx];
        }
    }
    if (tid == T - 1) g_rowptr[N_NODES] = run;
}

__global__ void fill_kernel() {
    int e = blockIdx.x * blockDim.x + threadIdx.x;
    if (e < N_EDGES) {
        int dst = g_dst[e];
        int slot = atomicAdd(&g_cur[dst], 1);
        g_nbr[slot] = g_src[e];
    }
}

// ---------------------------------------------------------------------------
// GEMM1 via WMMA tf32 + cp.async 3-stage pipeline:
//   PQ = x @ [W1l | W1r]   (b1 applied in gather1)
//   M=50048(pad), N=512 (grid.y: 0->W1l, 1->W1r), K=256.
//   CTA tile 128x256, BK=32, 8 warps as 2(m)x4(n), warp tile 64x64.
#define BM 128
#define BN 256
#define BK 32
#define KT (C / BK)            // 8 k-tiles
#define A_LD 36                // 32 + 4 pad
#define B_LD 260               // 256 + 4 pad
#define A_STG (BM * A_LD)      // floats per A stage
#define B_STG (BK * B_LD)      // floats per B stage
#define G1_SMEM_BYTES ((3 * A_STG + 3 * B_STG) * 4)   // 155,136 B

__global__ __launch_bounds__(256) void gemm1_kernel(
    const float* __restrict__ x,
    const float* __restrict__ W1l, const float* __restrict__ W1r) {
    extern __shared__ float smf[];
    float* const Asm = smf;                 // [3][BM][A_LD]
    float* const Bsm = smf + 3 * A_STG;     // [3][BK][B_LD]
    const uint32_t sA = smem_u32(Asm);
    const uint32_t sB = smem_u32(Bsm);

    const int tid = threadIdx.x;
    const int wid = tid >> 5;
    const int bm = blockIdx.x * BM;
    const int bnBase = blockIdx.y * 256;
    const float* __restrict__ Wb = blockIdx.y ? W1r : W1l;
    const int wm = (wid & 1) * 64;
    const int wn = (wid >> 1) * 64;

    wmma::fragment<wmma::accumulator, 16, 16, 8, float> acc[4][4];
#pragma unroll
    for (int mi = 0; mi < 4; mi++)
#pragma unroll
        for (int ni = 0; ni < 4; ni++) wmma::fill_fragment(acc[mi][ni], 0.f);

    auto load_stage = [&](int t, int stg) {
        const int k0 = t * BK;
        // A: 128x32 fp32 = 1024 x 16B chunks, 4 per thread
#pragma unroll
        for (int i = 0; i < 4; i++) {
            int q = tid + i * 256;
            int row = q >> 3, kc = (q & 7) << 2;
            uint32_t dst = sA + (uint32_t)(stg * A_STG + row * A_LD + kc) * 4u;
            cp16(dst, x + (size_t)(bm + row) * C + k0 + kc, (bm + row) < N_NODES);
        }
        // B: 32x256 fp32 = 2048 x 16B chunks, 8 per thread
#pragma unroll
        for (int i = 0; i < 8; i++) {
            int q = tid + i * 256;
            int kr = q >> 6, nc = (q & 63) << 2;
            uint32_t dst = sB + (uint32_t)(stg * B_STG + kr * B_LD + nc) * 4u;
            cp16(dst, Wb + (size_t)(k0 + kr) * C + nc, true);
        }
        asm volatile("cp.async.commit_group;");
    };

    load_stage(0, 0);
    load_stage(1, 1);

    for (int t = 0; t < KT; t++) {
        const int st = t % 3;
        asm volatile("cp.async.wait_group 1;");
        __syncthreads();
        if (t + 2 < KT) load_stage(t + 2, (t + 2) % 3);
        else asm volatile("cp.async.commit_group;");   // empty group keeps accounting uniform

        const float* As_st = Asm + st * A_STG;
        const float* Bs_st = Bsm + st * B_STG;
#pragma unroll
        for (int kk = 0; kk < BK; kk += 8) {
            wmma::fragment<wmma::matrix_a, 16, 16, 8, wmma::precision::tf32, wmma::row_major> af[4];
            wmma::fragment<wmma::matrix_b, 16, 16, 8, wmma::precision::tf32, wmma::row_major> bf[4];
#pragma unroll
            for (int mi = 0; mi < 4; mi++) {
                wmma::load_matrix_sync(af[mi], As_st + (wm + mi * 16) * A_LD + kk, A_LD);
#pragma unroll
                for (int e = 0; e < af[mi].num_elements; e++)
                    af[mi].x[e] = wmma::__float_to_tf32(af[mi].x[e]);
            }
#pragma unroll
            for (int ni = 0; ni < 4; ni++) {
                wmma::load_matrix_sync(bf[ni], Bs_st + kk * B_LD + wn + ni * 16, B_LD);
#pragma unroll
                for (int e = 0; e < bf[ni].num_elements; e++)
                    bf[ni].x[e] = wmma::__float_to_tf32(bf[ni].x[e]);
            }
#pragma unroll
            for (int mi = 0; mi < 4; mi++)
#pragma unroll
                for (int ni = 0; ni < 4; ni++)
                    wmma::mma_sync(acc[mi][ni], af[mi], bf[ni], acc[mi][ni]);
        }
    }

    // Epilogue: padded rows -> no bounds checks
#pragma unroll
    for (int mi = 0; mi < 4; mi++) {
        int row0 = bm + wm + mi * 16;
#pragma unroll
        for (int ni = 0; ni < 4; ni++) {
            int col0 = bnBase + wn + ni * 16;
            wmma::store_matrix_sync(&g_PQ[(size_t)row0 * (2 * C) + col0], acc[mi][ni],
                                    2 * C, wmma::mem_row_major);
        }
    }
}

// ---------------------------------------------------------------------------
// Gather1: h[n] = relu( mean_{j in N(n)} P[j] + Q[n] + b1 )   (CSR, no atomics)
__global__ __launch_bounds__(256) void gather1_kernel(const float* __restrict__ b1) {
    __shared__ int nb[256];
    const int n = blockIdx.x;
    const int c = threadIdx.x;
    const int beg = g_rowptr[n];
    const int end = g_rowptr[n + 1];

    float s0 = 0.f, s1 = 0.f, s2 = 0.f, s3 = 0.f;
    for (int j0 = beg; j0 < end; j0 += 256) {
        int cnt = min(256, end - j0);
        __syncthreads();
        if (c < cnt) nb[c] = g_nbr[j0 + c];
        __syncthreads();
        int j = 0;
        for (; j + 4 <= cnt; j += 4) {
            s0 += g_PQ[nb[j + 0] * (2 * C) + c];
            s1 += g_PQ[nb[j + 1] * (2 * C) + c];
            s2 += g_PQ[nb[j + 2] * (2 * C) + c];
            s3 += g_PQ[nb[j + 3] * (2 * C) + c];
        }
        for (; j < cnt; j++) s0 += g_PQ[nb[j] * (2 * C) + c];
    }
    float sum = (s0 + s1) + (s2 + s3);
    float q = g_PQ[n * (2 * C) + C + c] + b1[c];
    float h = fmaf(sum, g_inv[n], q);
    g_h[n * C + c] = fmaxf(h, 0.f);
}

// ---------------------------------------------------------------------------
// GEMM2: Rl = h @ W2l ; Rr = h @ W2r + b2.  Warp per node, K=256, N=10 each.
__global__ __launch_bounds__(256) void gemm2_kernel(
    const float* __restrict__ W2l, const float* __restrict__ W2r,
    const float* __restrict__ b2) {
    __shared__ __align__(16) float Wt[2 * OUTC][C];
    __shared__ float b2s[OUTC];

    const int tid = threadIdx.x;
    for (int p = tid; p < 2 * OUTC * C; p += 256) {
        int n = p / C, k = p % C;
        Wt[n][k] = (n < OUTC) ? W2l[k * OUTC + n] : W2r[k * OUTC + (n - OUTC)];
    }
    if (tid < OUTC) b2s[tid] = b2[tid];
    __syncthreads();

    const int lane = tid & 31;
    const int warp = tid >> 5;
    const int node = blockIdx.x * 8 + warp;
    if (node >= N_NODES) return;

    const float4* hr = (const float4*)(g_h + node * C);
    float4 h0 = hr[lane], h1 = hr[lane + 32];

    float s[2 * OUTC];
#pragma unroll
    for (int n = 0; n < 2 * OUTC; n++) {
        const float4* w = (const float4*)&Wt[n][0];
        float4 w0 = w[lane], w1 = w[lane + 32];
        float acc = h0.x * w0.x + h0.y * w0.y + h0.z * w0.z + h0.w * w0.w;
        acc += h1.x * w1.x + h1.y * w1.y + h1.z * w1.z + h1.w * w1.w;
#pragma unroll
        for (int off = 16; off; off >>= 1)
            acc += __shfl_xor_sync(0xffffffffu, acc, off);
        s[n] = acc;
    }
    if (lane == 0) {
#pragma unroll
        for (int n = 0; n < OUTC; n++) {
            g_Rl[node * OUTC + n] = s[n];
            g_Rr[node * OUTC + n] = s[OUTC + n] + b2s[n];
        }
    }
}

// ---------------------------------------------------------------------------
// Final: out[n] = log_softmax( mean_{j in N(n)} Rl[j] + Rr[n] )
__global__ __launch_bounds__(256) void final_kernel(float* __restrict__ out) {
    const int tid = threadIdx.x;
    const int lane = tid & 31;
    const int warp = tid >> 5;
    const int node = blockIdx.x * 8 + warp;
    if (node >= N_NODES) return;

    const int beg = g_rowptr[node];
    const int end = g_rowptr[node + 1];

    float sum = 0.f;
    const int t = lane;
    for (int j = beg; j < end; j++) {
        int src = g_nbr[j];
        if (t < OUTC) sum += g_Rl[src * OUTC + t];
    }
    float s = -FLT_MAX;
    if (t < OUTC) s = fmaf(sum, g_inv[node], g_Rr[node * OUTC + t]);

    float m = s;
#pragma unroll
    for (int off = 16; off; off >>= 1)
        m = fmaxf(m, __shfl_xor_sync(0xffffffffu, m, off));
    float e = (t < OUTC) ? expf(s - m) : 0.f;
#pragma unroll
    for (int off = 16; off; off >>= 1)
        e += __shfl_xor_sync(0xffffffffu, e, off);
    float lse = m + logf(e);
    if (t < OUTC) out[node * OUTC + t] = s - lse;
}

// ---------------------------------------------------------------------------
extern "C" void kernel_launch(void* const* d_in, const int* in_sizes, int n_in,
                              void* d_out, int out_size) {
    const float* x = (const float*)d_in[0];
    const void* ei = d_in[1];
    const float* W1l = (const float*)d_in[2];
    const float* W1r = (const float*)d_in[3];
    const float* b1 = (const float*)d_in[4];
    const float* W2l = (const float*)d_in[5];
    const float* W2r = (const float*)d_in[6];
    const float* b2 = (const float*)d_in[7];
    float* out = (float*)d_out;

    cudaFuncSetAttribute(gemm1_kernel,
                         cudaFuncAttributeMaxDynamicSharedMemorySize, G1_SMEM_BYTES);

    detect_kernel<<<1, 256>>>((const int*)ei);
    zero_cnt_kernel<<<(N_NODES + 255) / 256, 256>>>();
    convert_count_kernel<<<(N_EDGES + 255) / 256, 256>>>(ei);
    inv_kernel<<<(N_NODES + 255) / 256, 256>>>();
    scan_kernel<<<1, 1024>>>();
    fill_kernel<<<(N_EDGES + 255) / 256, 256>>>();

    dim3 g1(M_PAD / BM, 2);   // 391 x 2 (N=512 via W1l/W1r halves)
    gemm1_kernel<<<g1, 256, G1_SMEM_BYTES>>>(x, W1l, W1r);

    gather1_kernel<<<N_NODES, 256>>>(b1);

    gemm2_kernel<<<(N_NODES + 7) / 8, 256>>>(W2l, W2r, b2);
    final_kernel<<<(N_NODES + 7) / 8, 256>>>(out);
}

// round 16
// speedup vs baseline: 4.5201x; 1.1354x over previous
#include <cuda_runtime.h>
#include <cuda_fp16.h>
#include <mma.h>
#include <cstdint>
#include <float.h>

using namespace nvcuda;

#define N_NODES 50000
#define M_PAD 50048           // N_NODES rounded up to 128
#define N_EDGES 1600000
#define C 256
#define OUTC 10

// Scratch (device globals: allocation-free per harness rules)
__device__ __half g_Ph[M_PAD * C];        // x@W1l (P) in fp16  [50048,256]
__device__ float  g_Q[M_PAD * C];         // x@W1r (Q) fp32, bias added in gather
__device__ float  g_h[N_NODES * C];       // layer-1 output (relu)
__device__ float  g_Rl[N_NODES * OUTC];   // h @ W2l
__device__ float  g_Rr[N_NODES * OUTC];   // h @ W2r + b2
__device__ int    g_cnt[N_NODES];
__device__ float  g_inv[N_NODES];
__device__ int    g_rowptr[N_NODES + 1];
__device__ int    g_cur[N_NODES];
__device__ int    g_src[N_EDGES];
__device__ int    g_dst[N_EDGES];
__device__ int    g_nbr[N_EDGES];         // CSR adjacency (src nodes grouped by dst)
__device__ int    g_is64;

// ---------------------------------------------------------------------------
__device__ __forceinline__ uint32_t smem_u32(const void* p) {
    uint32_t a;
    asm("{ .reg .u64 t; cvta.to.shared.u64 t, %1; cvt.u32.u64 %0, t; }" : "=r"(a) : "l"(p));
    return a;
}
__device__ __forceinline__ void cp16(uint32_t dst, const void* src, bool pred) {
    int sz = pred ? 16 : 0;
    asm volatile("cp.async.cg.shared.global [%0], [%1], 16, %2;"
                 :: "r"(dst), "l"(src), "r"(sz));
}

// ---------------------------------------------------------------------------
// Edge preprocessing
__global__ void detect_kernel(const int* __restrict__ ei32) {
    __shared__ int any;
    if (threadIdx.x == 0) any = 0;
    __syncthreads();
    int nz = 0;
    for (int i = threadIdx.x; i < 4096; i += blockDim.x)
        if (ei32[2 * i + 1] != 0) nz = 1;
    if (nz) atomicOr(&any, 1);
    __syncthreads();
    if (threadIdx.x == 0) g_is64 = (any == 0);
}

__global__ void zero_cnt_kernel() {
    int i = blockIdx.x * blockDim.x + threadIdx.x;
    if (i < N_NODES) g_cnt[i] = 0;
}

__global__ void convert_count_kernel(const void* __restrict__ ei) {
    int e = blockIdx.x * blockDim.x + threadIdx.x;
    if (e >= N_EDGES) return;
    int s, d;
    if (g_is64) {
        const long long* __restrict__ p = (const long long*)ei;
        s = (int)p[e];
        d = (int)p[N_EDGES + e];
    } else {
        const int* __restrict__ p = (const int*)ei;
        s = p[e];
        d = p[N_EDGES + e];
    }
    g_src[e] = s;
    g_dst[e] = d;
    atomicAdd(&g_cnt[d], 1);
}

__global__ void inv_kernel() {
    int i = blockIdx.x * blockDim.x + threadIdx.x;
    if (i < N_NODES) {
        int c = g_cnt[i];
        g_inv[i] = 1.0f / (float)(c < 1 ? 1 : c);
    }
}

__global__ __launch_bounds__(1024) void scan_kernel() {
    __shared__ int partial[1024];
    const int T = 1024;
    const int CH = (N_NODES + T - 1) / T;
    int tid = threadIdx.x;
    int base = tid * CH;
    int s = 0;
    for (int i = 0; i < CH; i++) {
        int idx = base + i;
        if (idx < N_NODES) s += g_cnt[idx];
    }
    partial[tid] = s;
    __syncthreads();
    for (int off = 1; off < T; off <<= 1) {
        int v = (tid >= off) ? partial[tid - off] : 0;
        __syncthreads();
        partial[tid] += v;
        __syncthreads();
    }
    int run = (tid == 0) ? 0 : partial[tid - 1];
    for (int i = 0; i < CH; i++) {
        int idx = base + i;
        if (idx < N_NODES) {
            g_rowptr[idx] = run;
            g_cur[idx] = run;
            run += g_cnt[idx];
        }
    }
    if (tid == T - 1) g_rowptr[N_NODES] = run;
}

__global__ void fill_kernel() {
    int e = blockIdx.x * blockDim.x + threadIdx.x;
    if (e < N_EDGES) {
        int dst = g_dst[e];
        int slot = atomicAdd(&g_cur[dst], 1);
        g_nbr[slot] = g_src[e];
    }
}

// ---------------------------------------------------------------------------
// GEMM1 via WMMA tf32 + cp.async 3-stage pipeline.
//   grid.y==0: P = x @ W1l  -> fp16 g_Ph (via SMEM staging)
//   grid.y==1: Q = x @ W1r  -> fp32 g_Q
//   M=50048(pad), N=256, K=256. CTA tile 128x256, BK=32, 8 warps 2(m)x4(n).
#define BM 128
#define BK 32
#define KT (C / BK)            // 8 k-tiles
#define A_LD 36                // 32 + 4 pad
#define B_LD 260               // 256 + 4 pad
#define A_STG (BM * A_LD)      // floats per A stage
#define B_STG (BK * B_LD)      // floats per B stage
#define S_LD 260               // epilogue staging ld
#define G1_SMEM_BYTES ((3 * A_STG + 3 * B_STG) * 4)   // 155,136 B (>= 128*260*4 staging)

__global__ __launch_bounds__(256) void gemm1_kernel(
    const float* __restrict__ x,
    const float* __restrict__ W1l, const float* __restrict__ W1r) {
    extern __shared__ float smf[];
    float* const Asm = smf;                 // [3][BM][A_LD]
    float* const Bsm = smf + 3 * A_STG;     // [3][BK][B_LD]
    const uint32_t sA = smem_u32(Asm);
    const uint32_t sB = smem_u32(Bsm);

    const int tid = threadIdx.x;
    const int wid = tid >> 5;
    const int bm = blockIdx.x * BM;
    const float* __restrict__ Wb = blockIdx.y ? W1r : W1l;
    const int wm = (wid & 1) * 64;
    const int wn = (wid >> 1) * 64;

    wmma::fragment<wmma::accumulator, 16, 16, 8, float> acc[4][4];
#pragma unroll
    for (int mi = 0; mi < 4; mi++)
#pragma unroll
        for (int ni = 0; ni < 4; ni++) wmma::fill_fragment(acc[mi][ni], 0.f);

    auto load_stage = [&](int t, int stg) {
        const int k0 = t * BK;
#pragma unroll
        for (int i = 0; i < 4; i++) {
            int q = tid + i * 256;
            int row = q >> 3, kc = (q & 7) << 2;
            uint32_t dst = sA + (uint32_t)(stg * A_STG + row * A_LD + kc) * 4u;
            cp16(dst, x + (size_t)(bm + row) * C + k0 + kc, (bm + row) < N_NODES);
        }
#pragma unroll
        for (int i = 0; i < 8; i++) {
            int q = tid + i * 256;
            int kr = q >> 6, nc = (q & 63) << 2;
            uint32_t dst = sB + (uint32_t)(stg * B_STG + kr * B_LD + nc) * 4u;
            cp16(dst, Wb + (size_t)(k0 + kr) * C + nc, true);
        }
        asm volatile("cp.async.commit_group;");
    };

    load_stage(0, 0);
    load_stage(1, 1);

    for (int t = 0; t < KT; t++) {
        const int st = t % 3;
        asm volatile("cp.async.wait_group 1;");
        __syncthreads();
        if (t + 2 < KT) load_stage(t + 2, (t + 2) % 3);
        else asm volatile("cp.async.commit_group;");

        const float* As_st = Asm + st * A_STG;
        const float* Bs_st = Bsm + st * B_STG;
#pragma unroll
        for (int kk = 0; kk < BK; kk += 8) {
            wmma::fragment<wmma::matrix_a, 16, 16, 8, wmma::precision::tf32, wmma::row_major> af[4];
            wmma::fragment<wmma::matrix_b, 16, 16, 8, wmma::precision::tf32, wmma::row_major> bf[4];
#pragma unroll
            for (int mi = 0; mi < 4; mi++) {
                wmma::load_matrix_sync(af[mi], As_st + (wm + mi * 16) * A_LD + kk, A_LD);
#pragma unroll
                for (int e = 0; e < af[mi].num_elements; e++)
                    af[mi].x[e] = wmma::__float_to_tf32(af[mi].x[e]);
            }
#pragma unroll
            for (int ni = 0; ni < 4; ni++) {
                wmma::load_matrix_sync(bf[ni], Bs_st + kk * B_LD + wn + ni * 16, B_LD);
#pragma unroll
                for (int e = 0; e < bf[ni].num_elements; e++)
                    bf[ni].x[e] = wmma::__float_to_tf32(bf[ni].x[e]);
            }
#pragma unroll
            for (int mi = 0; mi < 4; mi++)
#pragma unroll
                for (int ni = 0; ni < 4; ni++)
                    wmma::mma_sync(acc[mi][ni], af[mi], bf[ni], acc[mi][ni]);
        }
    }

    if (blockIdx.y == 0) {
        // P pass: stage fp32 tile in SMEM, convert to fp16, write g_Ph
        asm volatile("cp.async.wait_group 0;");
        __syncthreads();   // mainloop SMEM dead; reuse as [128][S_LD] staging
#pragma unroll
        for (int mi = 0; mi < 4; mi++)
#pragma unroll
            for (int ni = 0; ni < 4; ni++)
                wmma::store_matrix_sync(smf + (wm + mi * 16) * S_LD + wn + ni * 16,
                                        acc[mi][ni], S_LD, wmma::mem_row_major);
        __syncthreads();
        for (int i = tid; i < 128 * 128; i += 256) {    // 128 rows x 128 half2
            int row = i >> 7, c2 = (i & 127) << 1;
            float2 v = *(float2*)&smf[row * S_LD + c2];
            *(__half2*)&g_Ph[(size_t)(bm + row) * C + c2] = __floats2half2_rn(v.x, v.y);
        }
    } else {
        // Q pass: fp32 direct
#pragma unroll
        for (int mi = 0; mi < 4; mi++) {
            int row0 = bm + wm + mi * 16;
#pragma unroll
            for (int ni = 0; ni < 4; ni++)
                wmma::store_matrix_sync(&g_Q[(size_t)row0 * C + wn + ni * 16],
                                        acc[mi][ni], C, wmma::mem_row_major);
        }
    }
}

// ---------------------------------------------------------------------------
// Gather1: h[n] = relu( mean_{j in N(n)} P[j] + Q[n] + b1 )
// 128 threads/node; thread t owns channel pair (2t, 2t+1) via half2.
__global__ __launch_bounds__(128) void gather1_kernel(const float* __restrict__ b1) {
    __shared__ int nb[128];
    const int n = blockIdx.x;
    const int t = threadIdx.x;
    const int beg = g_rowptr[n];
    const int end = g_rowptr[n + 1];
    const int c2 = t << 1;

    float2 s0 = make_float2(0.f, 0.f), s1 = s0, s2 = s0, s3 = s0;
    for (int j0 = beg; j0 < end; j0 += 128) {
        int cnt = min(128, end - j0);
        __syncthreads();
        if (t < cnt) nb[t] = g_nbr[j0 + t];
        __syncthreads();
        int j = 0;
        for (; j + 4 <= cnt; j += 4) {
            __half2 a = *(const __half2*)&g_Ph[(size_t)nb[j + 0] * C + c2];
            __half2 b = *(const __half2*)&g_Ph[(size_t)nb[j + 1] * C + c2];
            __half2 c = *(const __half2*)&g_Ph[(size_t)nb[j + 2] * C + c2];
            __half2 d = *(const __half2*)&g_Ph[(size_t)nb[j + 3] * C + c2];
            float2 fa = __half22float2(a), fb = __half22float2(b);
            float2 fc = __half22float2(c), fd = __half22float2(d);
            s0.x += fa.x; s0.y += fa.y;
            s1.x += fb.x; s1.y += fb.y;
            s2.x += fc.x; s2.y += fc.y;
            s3.x += fd.x; s3.y += fd.y;
        }
        for (; j < cnt; j++) {
            float2 f = __half22float2(*(const __half2*)&g_Ph[(size_t)nb[j] * C + c2]);
            s0.x += f.x; s0.y += f.y;
        }
    }
    float sx = (s0.x + s1.x) + (s2.x + s3.x);
    float sy = (s0.y + s1.y) + (s2.y + s3.y);
    float2 q = *(const float2*)&g_Q[(size_t)n * C + c2];
    float2 bb = *(const float2*)&b1[c2];
    float inv = g_inv[n];
    float hx = fmaf(sx, inv, q.x + bb.x);
    float hy = fmaf(sy, inv, q.y + bb.y);
    float2 o = make_float2(fmaxf(hx, 0.f), fmaxf(hy, 0.f));
    *(float2*)&g_h[(size_t)n * C + c2] = o;
}

// ---------------------------------------------------------------------------
// GEMM2: Rl = h @ W2l ; Rr = h @ W2r + b2.  Warp per node, K=256, N=10 each.
__global__ __launch_bounds__(256) void gemm2_kernel(
    const float* __restrict__ W2l, const float* __restrict__ W2r,
    const float* __restrict__ b2) {
    __shared__ __align__(16) float Wt[2 * OUTC][C];
    __shared__ float b2s[OUTC];

    const int tid = threadIdx.x;
    for (int p = tid; p < 2 * OUTC * C; p += 256) {
        int n = p / C, k = p % C;
        Wt[n][k] = (n < OUTC) ? W2l[k * OUTC + n] : W2r[k * OUTC + (n - OUTC)];
    }
    if (tid < OUTC) b2s[tid] = b2[tid];
    __syncthreads();

    const int lane = tid & 31;
    const int warp = tid >> 5;
    const int node = blockIdx.x * 8 + warp;
    if (node >= N_NODES) return;

    const float4* hr = (const float4*)(g_h + (size_t)node * C);
    float4 h0 = hr[lane], h1 = hr[lane + 32];

    float s[2 * OUTC];
#pragma unroll
    for (int n = 0; n < 2 * OUTC; n++) {
        const float4* w = (const float4*)&Wt[n][0];
        float4 w0 = w[lane], w1 = w[lane + 32];
        float acc = h0.x * w0.x + h0.y * w0.y + h0.z * w0.z + h0.w * w0.w;
        acc += h1.x * w1.x + h1.y * w1.y + h1.z * w1.z + h1.w * w1.w;
#pragma unroll
        for (int off = 16; off; off >>= 1)
            acc += __shfl_xor_sync(0xffffffffu, acc, off);
        s[n] = acc;
    }
    if (lane == 0) {
#pragma unroll
        for (int n = 0; n < OUTC; n++) {
            g_Rl[node * OUTC + n] = s[n];
            g_Rr[node * OUTC + n] = s[OUTC + n] + b2s[n];
        }
    }
}

// ---------------------------------------------------------------------------
// Final: out[n] = log_softmax( mean_{j in N(n)} Rl[j] + Rr[n] )
__global__ __launch_bounds__(256) void final_kernel(float* __restrict__ out) {
    const int tid = threadIdx.x;
    const int lane = tid & 31;
    const int warp = tid >> 5;
    const int node = blockIdx.x * 8 + warp;
    if (node >= N_NODES) return;

    const int beg = g_rowptr[node];
    const int end = g_rowptr[node + 1];

    float sum = 0.f;
    const int t = lane;
    for (int j = beg; j < end; j++) {
        int src = g_nbr[j];
        if (t < OUTC) sum += g_Rl[src * OUTC + t];
    }
    float s = -FLT_MAX;
    if (t < OUTC) s = fmaf(sum, g_inv[node], g_Rr[node * OUTC + t]);

    float m = s;
#pragma unroll
    for (int off = 16; off; off >>= 1)
        m = fmaxf(m, __shfl_xor_sync(0xffffffffu, m, off));
    float e = (t < OUTC) ? expf(s - m) : 0.f;
#pragma unroll
    for (int off = 16; off; off >>= 1)
        e += __shfl_xor_sync(0xffffffffu, e, off);
    float lse = m + logf(e);
    if (t < OUTC) out[node * OUTC + t] = s - lse;
}

// ---------------------------------------------------------------------------
extern "C" void kernel_launch(void* const* d_in, const int* in_sizes, int n_in,
                              void* d_out, int out_size) {
    const float* x = (const float*)d_in[0];
    const void* ei = d_in[1];
    const float* W1l = (const float*)d_in[2];
    const float* W1r = (const float*)d_in[3];
    const float* b1 = (const float*)d_in[4];
    const float* W2l = (const float*)d_in[5];
    const float* W2r = (const float*)d_in[6];
    const float* b2 = (const float*)d_in[7];
    float* out = (float*)d_out;

    cudaFuncSetAttribute(gemm1_kernel,
                         cudaFuncAttributeMaxDynamicSharedMemorySize, G1_SMEM_BYTES);

    detect_kernel<<<1, 256>>>((const int*)ei);
    zero_cnt_kernel<<<(N_NODES + 255) / 256, 256>>>();
    convert_count_kernel<<<(N_EDGES + 255) / 256, 256>>>(ei);
    inv_kernel<<<(N_NODES + 255) / 256, 256>>>();
    scan_kernel<<<1, 1024>>>();
    fill_kernel<<<(N_EDGES + 255) / 256, 256>>>();

    dim3 g1(M_PAD / BM, 2);   // y=0: P(fp16), y=1: Q(fp32)
    gemm1_kernel<<<g1, 256, G1_SMEM_BYTES>>>(x, W1l, W1r);

    gather1_kernel<<<N_NODES, 128>>>(b1);

    gemm2_kernel<<<(N_NODES + 7) / 8, 256>>>(W2l, W2r, b2);
    final_kernel<<<(N_NODES + 7) / 8, 256>>>(out);
}